// round 11
// baseline (speedup 1.0000x reference)
#include <cuda_runtime.h>
#include <cuda_bf16.h>
#include <cstdint>

#define D_MODEL 2048
#define R_DIM   512
#define N_HEADS 16
#define D_K     32
#define B_SZ    2
#define S_LEN   2048
#define M_ROWS  (B_SZ * S_LEN)   // 4096

typedef unsigned long long u64;
typedef uint32_t u32;

// ---------------------------------------------------------------------------
// bf16 hi/lo split storage
// ---------------------------------------------------------------------------
#define X_OFF   0ull
#define W_OFF   8388608ull
#define WSZ     1048576ull
#define WO_OFF  11534336ull
#define O_OFF   12582912ull
#define QKV_OFF 14680064ull
#define QKVSZ   2097152ull
#define SPLIT_TOTAL 20971520ull
__device__ __nv_bfloat16 g_hi[SPLIT_TOTAL];
__device__ __nv_bfloat16 g_lo[SPLIT_TOTAL];

// ---------------------------------------------------------------------------
// PTX helpers (base ISA only: mma.sync / ldmatrix / cp.async)
// ---------------------------------------------------------------------------
__device__ __forceinline__ u32 smem_u32(const void* p) {
    u32 a;
    asm("{ .reg .u64 t; cvta.to.shared.u64 t, %1; cvt.u32.u64 %0, t; }" : "=r"(a) : "l"(p));
    return a;
}
__device__ __forceinline__ void ldsm_x4(u32& r0, u32& r1, u32& r2, u32& r3, u32 addr) {
    asm volatile("ldmatrix.sync.aligned.m8n8.x4.shared.b16 {%0,%1,%2,%3}, [%4];"
                 : "=r"(r0), "=r"(r1), "=r"(r2), "=r"(r3) : "r"(addr));
}
__device__ __forceinline__ void ldsm_x4_t(u32& r0, u32& r1, u32& r2, u32& r3, u32 addr) {
    asm volatile("ldmatrix.sync.aligned.m8n8.x4.trans.shared.b16 {%0,%1,%2,%3}, [%4];"
                 : "=r"(r0), "=r"(r1), "=r"(r2), "=r"(r3) : "r"(addr));
}
__device__ __forceinline__ void mma_bf16(float* d, const u32* a, const u32* b) {
    asm volatile(
        "mma.sync.aligned.m16n8k16.row.col.f32.bf16.bf16.f32 "
        "{%0,%1,%2,%3}, {%4,%5,%6,%7}, {%8,%9}, {%0,%1,%2,%3};"
        : "+f"(d[0]), "+f"(d[1]), "+f"(d[2]), "+f"(d[3])
        : "r"(a[0]), "r"(a[1]), "r"(a[2]), "r"(a[3]), "r"(b[0]), "r"(b[1]));
}
__device__ __forceinline__ void cp16(u32 saddr, const void* g) {
    asm volatile("cp.async.cg.shared.global [%0], [%1], 16;" :: "r"(saddr), "l"(g) : "memory");
}
__device__ __forceinline__ void cp_commit() {
    asm volatile("cp.async.commit_group;" ::: "memory");
}
__device__ __forceinline__ u32 pack_split(float x, float y, u32& lo_out) {
    __nv_bfloat162 h = __floats2bfloat162_rn(x, y);
    float hx = __bfloat162float(h.x), hy = __bfloat162float(h.y);
    __nv_bfloat162 l = __floats2bfloat162_rn(x - hx, y - hy);
    lo_out = *reinterpret_cast<u32*>(&l);
    return *reinterpret_cast<u32*>(&h);
}

// ---------------------------------------------------------------------------
// fp32 -> bf16 hi/lo split: single fused launch over x + 4 weight matrices
// segment float4 counts: x 2097152, each W 262144 (cumulative below)
// ---------------------------------------------------------------------------
__global__ __launch_bounds__(256) void convert_all_kernel(
    const float* __restrict__ x,  const float* __restrict__ Wq,
    const float* __restrict__ Wk, const float* __restrict__ Wv,
    const float* __restrict__ Wo)
{
    int i = blockIdx.x * blockDim.x + threadIdx.x;
    const float* src; size_t dst; int idx;
    if (i < 2097152)      { src = x;  dst = X_OFF;           idx = i; }
    else if (i < 2359296) { src = Wq; dst = W_OFF;           idx = i - 2097152; }
    else if (i < 2621440) { src = Wk; dst = W_OFF + WSZ;     idx = i - 2359296; }
    else if (i < 2883584) { src = Wv; dst = W_OFF + 2 * WSZ; idx = i - 2621440; }
    else                  { src = Wo; dst = WO_OFF;          idx = i - 2883584; }

    float4 v = ((const float4*)src)[idx];
    __nv_bfloat16 h0 = __float2bfloat16(v.x);
    __nv_bfloat16 h1 = __float2bfloat16(v.y);
    __nv_bfloat16 h2 = __float2bfloat16(v.z);
    __nv_bfloat16 h3 = __float2bfloat16(v.w);
    __nv_bfloat16 l0 = __float2bfloat16(v.x - __bfloat162float(h0));
    __nv_bfloat16 l1 = __float2bfloat16(v.y - __bfloat162float(h1));
    __nv_bfloat16 l2 = __float2bfloat16(v.z - __bfloat162float(h2));
    __nv_bfloat16 l3 = __float2bfloat16(v.w - __bfloat162float(h3));
    __nv_bfloat162 ph0; ph0.x = h0; ph0.y = h1;
    __nv_bfloat162 ph1; ph1.x = h2; ph1.y = h3;
    __nv_bfloat162 pl0; pl0.x = l0; pl0.y = l1;
    __nv_bfloat162 pl1; pl1.x = l2; pl1.y = l3;
    ((__nv_bfloat162*)(g_hi + dst))[2 * idx + 0] = ph0;
    ((__nv_bfloat162*)(g_hi + dst))[2 * idx + 1] = ph1;
    ((__nv_bfloat162*)(g_lo + dst))[2 * idx + 0] = pl0;
    ((__nv_bfloat162*)(g_lo + dst))[2 * idx + 1] = pl1;
}

// ---------------------------------------------------------------------------
// HMMA bf16-split GEMM: 3-stage cp.async pipeline, one sync per chunk.
// ---------------------------------------------------------------------------
#define BM 128
#define BN 128
#define BK 64

#define TILE_B      (128 * 128)
#define STAGE_BYTES (4 * TILE_B)          // 64 KB
#define SM_TOTAL    (3 * STAGE_BYTES)     // 192 KB

__device__ __forceinline__ void gemm_hmma(
    const __nv_bfloat16* __restrict__ ah, const __nv_bfloat16* __restrict__ al,
    const __nv_bfloat16* __restrict__ bh, const __nv_bfloat16* __restrict__ bl,
    const float* __restrict__ bias, float* __restrict__ C,
    __nv_bfloat16* __restrict__ outH, __nv_bfloat16* __restrict__ outL, float oscale,
    int K, int ldc, int bm, int bn)
{
    extern __shared__ char smem[];
    const u32 sbase = smem_u32(smem);
    const int tid  = threadIdx.x;
    const int lane = tid & 31;
    const int wid  = tid >> 5;
    const int wm   = wid & 3;
    const int wn   = wid >> 2;

    float acc[2][8][4];
    #pragma unroll
    for (int mt = 0; mt < 2; mt++)
        #pragma unroll
        for (int nt = 0; nt < 8; nt++)
            #pragma unroll
            for (int r = 0; r < 4; r++) acc[mt][nt][r] = 0.f;

    auto load_stage = [&](int c, int stage) {
        const int k0 = c * BK;
        const u32 sb = sbase + stage * STAGE_BYTES;
        #pragma unroll
        for (int t = 0; t < 16; t++) {
            int i   = tid + t * 256;
            int arr = i >> 10;
            int ch  = i & 1023;
            int row = ch >> 3;
            int cc  = ch & 7;
            u32 soff = (u32)arr * TILE_B + (u32)row * 128 + (u32)((cc ^ (row & 7)) << 4);
            const __nv_bfloat16* g;
            if (arr == 0)      g = ah + (size_t)(bm + row) * K + k0 + cc * 8;
            else if (arr == 1) g = al + (size_t)(bm + row) * K + k0 + cc * 8;
            else if (arr == 2) g = bh + (size_t)(bn + row) * K + k0 + cc * 8;
            else               g = bl + (size_t)(bn + row) * K + k0 + cc * 8;
            cp16(sb + soff, g);
        }
        cp_commit();
    };

    auto compute_stage = [&](int stage) {
        const u32 sb = sbase + stage * STAGE_BYTES;
        #pragma unroll
        for (int ks = 0; ks < 4; ks++) {
            u32 a_h[2][4], a_l[2][4], b_h[8][2], b_l[8][2];
            #pragma unroll
            for (int mt = 0; mt < 2; mt++) {
                int row = wm * 32 + mt * 16 + (lane & 15);
                u32 koff = (u32)(((2 * ks + (lane >> 4)) ^ (row & 7)) << 4);
                u32 addr = sb + (u32)row * 128 + koff;
                ldsm_x4(a_h[mt][0], a_h[mt][1], a_h[mt][2], a_h[mt][3], addr);
                ldsm_x4(a_l[mt][0], a_l[mt][1], a_l[mt][2], a_l[mt][3], addr + TILE_B);
            }
            #pragma unroll
            for (int np = 0; np < 4; np++) {
                int row = wn * 64 + np * 16 + (lane & 15);
                u32 koff = (u32)(((2 * ks + (lane >> 4)) ^ (row & 7)) << 4);
                u32 addr = sb + 2u * TILE_B + (u32)row * 128 + koff;
                u32 r0, r1, r2, r3;
                ldsm_x4(r0, r1, r2, r3, addr);
                b_h[2 * np][0] = r0; b_h[2 * np][1] = r2;
                b_h[2 * np + 1][0] = r1; b_h[2 * np + 1][1] = r3;
                ldsm_x4(r0, r1, r2, r3, addr + TILE_B);
                b_l[2 * np][0] = r0; b_l[2 * np][1] = r2;
                b_l[2 * np + 1][0] = r1; b_l[2 * np + 1][1] = r3;
            }
            #pragma unroll
            for (int mt = 0; mt < 2; mt++)
                #pragma unroll
                for (int nt = 0; nt < 8; nt++) {
                    mma_bf16(acc[mt][nt], a_h[mt], b_h[nt]);
                    mma_bf16(acc[mt][nt], a_h[mt], b_l[nt]);
                    mma_bf16(acc[mt][nt], a_l[mt], b_h[nt]);
                }
        }
    };

    const int nch = K >> 6;        // >= 8 always here
    load_stage(0, 0);
    load_stage(1, 1);
    int cur = 0;                   // stage of chunk c
    for (int c = 0; c < nch; c++) {
        if (c == nch - 1) {
            asm volatile("cp.async.wait_group 0;" ::: "memory");
        } else {
            asm volatile("cp.async.wait_group 1;" ::: "memory");
        }
        __syncthreads();
        if (c + 2 < nch) {
            int nxt2 = cur + 2; if (nxt2 >= 3) nxt2 -= 3;
            load_stage(c + 2, nxt2);
        }
        compute_stage(cur);
        if (++cur == 3) cur = 0;
    }

    const int g  = lane >> 2;
    const int tc = lane & 3;
    if (outH) {
        #pragma unroll
        for (int mt = 0; mt < 2; mt++) {
            #pragma unroll
            for (int nt = 0; nt < 8; nt++) {
                int row = bm + wm * 32 + mt * 16 + g;
                int col = bn + wn * 64 + nt * 8 + 2 * tc;
                float b0 = bias[col], b1 = bias[col + 1];
                float f0 = (acc[mt][nt][0] + b0) * oscale;
                float f1 = (acc[mt][nt][1] + b1) * oscale;
                float f2 = (acc[mt][nt][2] + b0) * oscale;
                float f3 = (acc[mt][nt][3] + b1) * oscale;
                u32 lo01, lo23;
                u32 hi01 = pack_split(f0, f1, lo01);
                u32 hi23 = pack_split(f2, f3, lo23);
                size_t o0 = (size_t)row * ldc + col;
                size_t o1 = (size_t)(row + 8) * ldc + col;
                *(u32*)&outH[o0] = hi01; *(u32*)&outL[o0] = lo01;
                *(u32*)&outH[o1] = hi23; *(u32*)&outL[o1] = lo23;
            }
        }
    } else {
        #pragma unroll
        for (int mt = 0; mt < 2; mt++) {
            #pragma unroll
            for (int nt = 0; nt < 8; nt++) {
                int row = bm + wm * 32 + mt * 16 + g;
                int col = bn + wn * 64 + nt * 8 + 2 * tc;
                float b0 = bias[col], b1 = bias[col + 1];
                float2 v0; v0.x = acc[mt][nt][0] + b0; v0.y = acc[mt][nt][1] + b1;
                float2 v1; v1.x = acc[mt][nt][2] + b0; v1.y = acc[mt][nt][3] + b1;
                *(float2*)&C[(size_t)row * ldc + col]       = v0;
                *(float2*)&C[(size_t)(row + 8) * ldc + col] = v1;
            }
        }
    }
}

__global__ __launch_bounds__(256) void qkv_hmma_kernel(
    const float* __restrict__ bq, const float* __restrict__ bk, const float* __restrict__ bv)
{
    const int z = blockIdx.z;
    const float* bias = (z == 0) ? bq : (z == 1) ? bk : bv;
    const float scale = (z == 0) ? 0.17677669529663687f : 1.0f;
    gemm_hmma(g_hi + X_OFF, g_lo + X_OFF,
              g_hi + W_OFF + (size_t)z * WSZ, g_lo + W_OFF + (size_t)z * WSZ,
              bias, nullptr,
              g_hi + QKV_OFF + (size_t)z * QKVSZ, g_lo + QKV_OFF + (size_t)z * QKVSZ, scale,
              D_MODEL, R_DIM, blockIdx.y * BM, blockIdx.x * BN);
}

__global__ __launch_bounds__(256) void outproj_hmma_kernel(
    const float* __restrict__ bo, float* __restrict__ out)
{
    gemm_hmma(g_hi + O_OFF, g_lo + O_OFF,
              g_hi + WO_OFF, g_lo + WO_OFF,
              bo, out, nullptr, nullptr, 1.0f,
              R_DIM, D_MODEL, blockIdx.y * BM, blockIdx.x * BN);
}

// ---------------------------------------------------------------------------
// HMMA flash attention: 3-stage cp.async KV pipeline, one sync per chunk.
// ---------------------------------------------------------------------------
#define ATT_BQ  128
#define ATT_BKV 128
#define ROWB    80

#define AQ_H   0
#define AQ_L   10240
#define ASTG0  20480
#define ASTG   41472              // stage: Kh,Kl,Vh,Vl (4*10240) + 512 mask
#define AS_KH  0
#define AS_KL  10240
#define AS_VH  20480
#define AS_VL  30720
#define AS_MSK 40960
#define ATT_SMEM (20480 + 3 * 41472)   // 144896

__global__ __launch_bounds__(256, 1) void attn_hmma_kernel(const int* __restrict__ mask)
{
    extern __shared__ char smem[];
    const u32 sb = smem_u32(smem);
    const int tid  = threadIdx.x;
    const int lane = tid & 31;
    const int w    = tid >> 5;
    const int bh   = blockIdx.y;
    const int b    = bh >> 4;
    const int h    = bh & 15;
    const int q0   = blockIdx.x * ATT_BQ;
    const int g    = lane >> 2;
    const int tc   = lane & 3;

    const __nv_bfloat16* Qh = g_hi + QKV_OFF;
    const __nv_bfloat16* Ql = g_lo + QKV_OFF;
    const __nv_bfloat16* Kh = g_hi + QKV_OFF + QKVSZ;
    const __nv_bfloat16* Kl = g_lo + QKV_OFF + QKVSZ;
    const __nv_bfloat16* Vh = g_hi + QKV_OFF + 2 * QKVSZ;
    const __nv_bfloat16* Vl = g_lo + QKV_OFF + 2 * QKVSZ;
    __nv_bfloat16* Oh = g_hi + O_OFF;
    __nv_bfloat16* Ol = g_lo + O_OFF;

    // ---- KV stage loader ----
    auto load_kv = [&](int k0, int stage) {
        const u32 stg = sb + ASTG0 + stage * ASTG;
        #pragma unroll
        for (int t = 0; t < 8; t++) {
            int c   = tid + t * 256;
            int arr = c >> 9;      // 0:Kh 1:Kl 2:Vh 3:Vl
            int wch = c & 511;
            int row = wch >> 2;
            int prt = wch & 3;
            const __nv_bfloat16* src;
            if (arr == 0)      src = Kh;
            else if (arr == 1) src = Kl;
            else if (arr == 2) src = Vh;
            else               src = Vl;
            src += (size_t)(b * S_LEN + k0 + row) * R_DIM + h * D_K + prt * 8;
            cp16(stg + arr * 10240u + (u32)row * ROWB + (u32)prt * 16, src);
        }
        if (tid < 32)
            cp16(stg + AS_MSK + tid * 16, mask + b * S_LEN + k0 + tid * 4);
        cp_commit();
    };

    // ---- prologue: Q stage, then KV stages 0 and 1 ----
    #pragma unroll
    for (int t = 0; t < 4; t++) {
        int c   = tid + t * 256;
        int arr = c >> 9;
        int wch = c & 511;
        int row = wch >> 2;
        int prt = wch & 3;
        const __nv_bfloat16* src = (arr ? Ql : Qh)
            + (size_t)(b * S_LEN + q0 + row) * R_DIM + h * D_K + prt * 8;
        cp16(sb + (arr ? AQ_L : AQ_H) + row * ROWB + prt * 16, src);
    }
    cp_commit();
    load_kv(0, 0);
    load_kv(ATT_BKV, 1);

    asm volatile("cp.async.wait_group 2;" ::: "memory");   // Q ready
    __syncthreads();

    u32 aqh[2][4], aql[2][4];
    #pragma unroll
    for (int kk = 0; kk < 2; kk++) {
        u32 addr = sb + AQ_H + (u32)(w * 16 + (lane & 15)) * ROWB + kk * 32 + (lane >> 4) * 16;
        ldsm_x4(aqh[kk][0], aqh[kk][1], aqh[kk][2], aqh[kk][3], addr);
        ldsm_x4(aql[kk][0], aql[kk][1], aql[kk][2], aql[kk][3], addr + (AQ_L - AQ_H));
    }

    float m0 = -1e30f, m1 = -1e30f, l0 = 0.f, l1 = 0.f;
    float ao[4][4];
    #pragma unroll
    for (int nt = 0; nt < 4; nt++)
        #pragma unroll
        for (int r = 0; r < 4; r++) ao[nt][r] = 0.f;

    const int nchunks = S_LEN / ATT_BKV;   // 16
    int cur = 0;
    for (int c = 0; c < nchunks; c++) {
        if (c == nchunks - 1) {
            asm volatile("cp.async.wait_group 0;" ::: "memory");
        } else {
            asm volatile("cp.async.wait_group 1;" ::: "memory");
        }
        __syncthreads();
        if (c + 2 < nchunks) {
            int nxt2 = cur + 2; if (nxt2 >= 3) nxt2 -= 3;
            load_kv((c + 2) * ATT_BKV, nxt2);
        }
        const u32 stg = sb + ASTG0 + cur * ASTG;
        const u32 stgoff = ASTG0 + cur * ASTG;

        // ---- scores ----
        float sc[16][4];
        #pragma unroll
        for (int p8 = 0; p8 < 8; p8++) {
            #pragma unroll
            for (int r = 0; r < 4; r++) { sc[2 * p8][r] = 0.f; sc[2 * p8 + 1][r] = 0.f; }
            #pragma unroll
            for (int kk = 0; kk < 2; kk++) {
                u32 addr = stg + AS_KH + (u32)(p8 * 16 + (lane & 15)) * ROWB + kk * 32 + (lane >> 4) * 16;
                u32 rh0, rh1, rh2, rh3, rl0, rl1, rl2, rl3;
                ldsm_x4(rh0, rh1, rh2, rh3, addr);
                ldsm_x4(rl0, rl1, rl2, rl3, addr + (AS_KL - AS_KH));
                u32 beh[2] = {rh0, rh2}, boh[2] = {rh1, rh3};
                u32 bel[2] = {rl0, rl2}, bol[2] = {rl1, rl3};
                mma_bf16(sc[2 * p8], aqh[kk], beh);
                mma_bf16(sc[2 * p8], aqh[kk], bel);
                mma_bf16(sc[2 * p8], aql[kk], beh);
                mma_bf16(sc[2 * p8 + 1], aqh[kk], boh);
                mma_bf16(sc[2 * p8 + 1], aqh[kk], bol);
                mma_bf16(sc[2 * p8 + 1], aql[kk], boh);
            }
        }

        // ---- online softmax ----
        float mt0 = m0, mt1 = m1;
        #pragma unroll
        for (int nt = 0; nt < 16; nt++) {
            int mi0 = *(const int*)(smem + stgoff + AS_MSK + (nt * 8 + 2 * tc) * 4);
            int mi1 = *(const int*)(smem + stgoff + AS_MSK + (nt * 8 + 2 * tc + 1) * 4);
            float md0 = mi0 ? 0.f : -1e30f;
            float md1 = mi1 ? 0.f : -1e30f;
            sc[nt][0] += md0; sc[nt][1] += md1;
            sc[nt][2] += md0; sc[nt][3] += md1;
            mt0 = fmaxf(mt0, fmaxf(sc[nt][0], sc[nt][1]));
            mt1 = fmaxf(mt1, fmaxf(sc[nt][2], sc[nt][3]));
        }
        mt0 = fmaxf(mt0, __shfl_xor_sync(0xFFFFFFFFu, mt0, 1));
        mt0 = fmaxf(mt0, __shfl_xor_sync(0xFFFFFFFFu, mt0, 2));
        mt1 = fmaxf(mt1, __shfl_xor_sync(0xFFFFFFFFu, mt1, 1));
        mt1 = fmaxf(mt1, __shfl_xor_sync(0xFFFFFFFFu, mt1, 2));
        float corr0 = __expf(m0 - mt0);
        float corr1 = __expf(m1 - mt1);
        m0 = mt0; m1 = mt1;
        float ls0 = 0.f, ls1 = 0.f;
        #pragma unroll
        for (int nt = 0; nt < 16; nt++) {
            sc[nt][0] = __expf(sc[nt][0] - m0);
            sc[nt][1] = __expf(sc[nt][1] - m0);
            sc[nt][2] = __expf(sc[nt][2] - m1);
            sc[nt][3] = __expf(sc[nt][3] - m1);
            ls0 += sc[nt][0] + sc[nt][1];
            ls1 += sc[nt][2] + sc[nt][3];
        }
        ls0 += __shfl_xor_sync(0xFFFFFFFFu, ls0, 1);
        ls0 += __shfl_xor_sync(0xFFFFFFFFu, ls0, 2);
        ls1 += __shfl_xor_sync(0xFFFFFFFFu, ls1, 1);
        ls1 += __shfl_xor_sync(0xFFFFFFFFu, ls1, 2);
        l0 = l0 * corr0 + ls0;
        l1 = l1 * corr1 + ls1;
        #pragma unroll
        for (int nt = 0; nt < 4; nt++) {
            ao[nt][0] *= corr0; ao[nt][1] *= corr0;
            ao[nt][2] *= corr1; ao[nt][3] *= corr1;
        }

        // ---- P @ V ----
        #pragma unroll
        for (int jc = 0; jc < 8; jc++) {
            u32 ah[4], al[4];
            ah[0] = pack_split(sc[2 * jc][0],     sc[2 * jc][1],     al[0]);
            ah[1] = pack_split(sc[2 * jc][2],     sc[2 * jc][3],     al[1]);
            ah[2] = pack_split(sc[2 * jc + 1][0], sc[2 * jc + 1][1], al[2]);
            ah[3] = pack_split(sc[2 * jc + 1][2], sc[2 * jc + 1][3], al[3]);
            #pragma unroll
            for (int np = 0; np < 2; np++) {
                u32 addr = stg + AS_VH
                         + (u32)(jc * 16 + ((lane >> 3) & 1) * 8 + (lane & 7)) * ROWB
                         + (u32)(np * 16 + (lane >> 4) * 8) * 2;
                u32 th0, th1, th2, th3, tl0, tl1, tl2, tl3;
                ldsm_x4_t(th0, th1, th2, th3, addr);
                ldsm_x4_t(tl0, tl1, tl2, tl3, addr + (AS_VL - AS_VH));
                u32 beh[2] = {th0, th1}, boh[2] = {th2, th3};
                u32 bel[2] = {tl0, tl1}, bol[2] = {tl2, tl3};
                mma_bf16(ao[2 * np], ah, beh);
                mma_bf16(ao[2 * np], ah, bel);
                mma_bf16(ao[2 * np], al, beh);
                mma_bf16(ao[2 * np + 1], ah, boh);
                mma_bf16(ao[2 * np + 1], ah, bol);
                mma_bf16(ao[2 * np + 1], al, boh);
            }
        }
        if (++cur == 3) cur = 0;
    }

    // ---- epilogue ----
    const float inv0 = 1.0f / l0;
    const float inv1 = 1.0f / l1;
    const int row0 = q0 + w * 16 + g;
    #pragma unroll
    for (int nt = 0; nt < 4; nt++) {
        int col = h * D_K + nt * 8 + 2 * tc;
        float f0 = ao[nt][0] * inv0, f1 = ao[nt][1] * inv0;
        float f2 = ao[nt][2] * inv1, f3 = ao[nt][3] * inv1;
        u32 lo01, lo23;
        u32 hi01 = pack_split(f0, f1, lo01);
        u32 hi23 = pack_split(f2, f3, lo23);
        size_t o0 = (size_t)(b * S_LEN + row0) * R_DIM + col;
        size_t o1 = (size_t)(b * S_LEN + row0 + 8) * R_DIM + col;
        *(u32*)&Oh[o0] = hi01;
        *(u32*)&Ol[o0] = lo01;
        *(u32*)&Oh[o1] = hi23;
        *(u32*)&Ol[o1] = lo23;
    }
}

// ---------------------------------------------------------------------------
extern "C" void kernel_launch(void* const* d_in, const int* in_sizes, int n_in,
                              void* d_out, int out_size)
{
    const float* x    = (const float*)d_in[0];
    const float* Wq   = (const float*)d_in[1];
    const float* bq   = (const float*)d_in[2];
    const float* Wk   = (const float*)d_in[3];
    const float* bk   = (const float*)d_in[4];
    const float* Wv   = (const float*)d_in[5];
    const float* bv   = (const float*)d_in[6];
    const float* Wo   = (const float*)d_in[7];
    const float* bo   = (const float*)d_in[8];
    const int*   mask = (const int*)d_in[9];
    float* out = (float*)d_out;

    cudaFuncSetAttribute(qkv_hmma_kernel, cudaFuncAttributeMaxDynamicSharedMemorySize, SM_TOTAL);
    cudaFuncSetAttribute(outproj_hmma_kernel, cudaFuncAttributeMaxDynamicSharedMemorySize, SM_TOTAL);
    cudaFuncSetAttribute(attn_hmma_kernel, cudaFuncAttributeMaxDynamicSharedMemorySize, ATT_SMEM);

    // 1) fp32 -> bf16 hi/lo splits, single fused launch (3145728 float4 total)
    convert_all_kernel<<<12288, 256>>>(x, Wq, Wk, Wv, Wo);

    // 2) QKV projections (HMMA), bf16 hi/lo output, Q pre-scaled
    dim3 g_qkv(R_DIM / BN, M_ROWS / BM, 3);
    qkv_hmma_kernel<<<g_qkv, 256, SM_TOTAL>>>(bq, bk, bv);

    // 3) flash attention (HMMA, 3-stage cp.async KV pipeline)
    dim3 g_attn(S_LEN / ATT_BQ, B_SZ * N_HEADS);
    attn_hmma_kernel<<<g_attn, 256, ATT_SMEM>>>(mask);

    // 4) output projection (HMMA)
    dim3 g_out(D_MODEL / BN, M_ROWS / BM);
    outproj_hmma_kernel<<<g_out, 256, SM_TOTAL>>>(bo, out);
}

// round 13
// speedup vs baseline: 1.0020x; 1.0020x over previous
#include <cuda_runtime.h>
#include <cuda_bf16.h>
#include <cstdint>

#define D_MODEL 2048
#define R_DIM   512
#define N_HEADS 16
#define D_K     32
#define B_SZ    2
#define S_LEN   2048
#define M_ROWS  (B_SZ * S_LEN)   // 4096

typedef unsigned long long u64;
typedef uint32_t u32;

// ---------------------------------------------------------------------------
// bf16 hi/lo split storage
// ---------------------------------------------------------------------------
#define X_OFF   0ull
#define W_OFF   8388608ull
#define WSZ     1048576ull
#define WO_OFF  11534336ull
#define O_OFF   12582912ull
#define QKV_OFF 14680064ull
#define QKVSZ   2097152ull
#define SPLIT_TOTAL 20971520ull
__device__ __nv_bfloat16 g_hi[SPLIT_TOTAL];
__device__ __nv_bfloat16 g_lo[SPLIT_TOTAL];

// ---------------------------------------------------------------------------
// PTX helpers (base ISA only: mma.sync / ldmatrix / cp.async)
// ---------------------------------------------------------------------------
__device__ __forceinline__ u32 smem_u32(const void* p) {
    u32 a;
    asm("{ .reg .u64 t; cvta.to.shared.u64 t, %1; cvt.u32.u64 %0, t; }" : "=r"(a) : "l"(p));
    return a;
}
__device__ __forceinline__ void ldsm_x4(u32& r0, u32& r1, u32& r2, u32& r3, u32 addr) {
    asm volatile("ldmatrix.sync.aligned.m8n8.x4.shared.b16 {%0,%1,%2,%3}, [%4];"
                 : "=r"(r0), "=r"(r1), "=r"(r2), "=r"(r3) : "r"(addr));
}
__device__ __forceinline__ void ldsm_x4_t(u32& r0, u32& r1, u32& r2, u32& r3, u32 addr) {
    asm volatile("ldmatrix.sync.aligned.m8n8.x4.trans.shared.b16 {%0,%1,%2,%3}, [%4];"
                 : "=r"(r0), "=r"(r1), "=r"(r2), "=r"(r3) : "r"(addr));
}
__device__ __forceinline__ void mma_bf16(float* d, const u32* a, const u32* b) {
    asm volatile(
        "mma.sync.aligned.m16n8k16.row.col.f32.bf16.bf16.f32 "
        "{%0,%1,%2,%3}, {%4,%5,%6,%7}, {%8,%9}, {%0,%1,%2,%3};"
        : "+f"(d[0]), "+f"(d[1]), "+f"(d[2]), "+f"(d[3])
        : "r"(a[0]), "r"(a[1]), "r"(a[2]), "r"(a[3]), "r"(b[0]), "r"(b[1]));
}
__device__ __forceinline__ void cp16(u32 saddr, const void* g) {
    asm volatile("cp.async.cg.shared.global [%0], [%1], 16;" :: "r"(saddr), "l"(g) : "memory");
}
__device__ __forceinline__ void cp_commit() {
    asm volatile("cp.async.commit_group;" ::: "memory");
}
__device__ __forceinline__ u32 pack_split(float x, float y, u32& lo_out) {
    __nv_bfloat162 h = __floats2bfloat162_rn(x, y);
    float hx = __bfloat162float(h.x), hy = __bfloat162float(h.y);
    __nv_bfloat162 l = __floats2bfloat162_rn(x - hx, y - hy);
    lo_out = *reinterpret_cast<u32*>(&l);
    return *reinterpret_cast<u32*>(&h);
}

// ---------------------------------------------------------------------------
// fp32 -> bf16 hi/lo split: single fused launch over x + 4 weight matrices
// segment float4 counts: x 2097152, each W 262144 (cumulative below)
// ---------------------------------------------------------------------------
__global__ __launch_bounds__(256) void convert_all_kernel(
    const float* __restrict__ x,  const float* __restrict__ Wq,
    const float* __restrict__ Wk, const float* __restrict__ Wv,
    const float* __restrict__ Wo)
{
    int i = blockIdx.x * blockDim.x + threadIdx.x;
    const float* src; size_t dst; int idx;
    if (i < 2097152)      { src = x;  dst = X_OFF;           idx = i; }
    else if (i < 2359296) { src = Wq; dst = W_OFF;           idx = i - 2097152; }
    else if (i < 2621440) { src = Wk; dst = W_OFF + WSZ;     idx = i - 2359296; }
    else if (i < 2883584) { src = Wv; dst = W_OFF + 2 * WSZ; idx = i - 2621440; }
    else                  { src = Wo; dst = WO_OFF;          idx = i - 2883584; }

    float4 v = ((const float4*)src)[idx];
    __nv_bfloat16 h0 = __float2bfloat16(v.x);
    __nv_bfloat16 h1 = __float2bfloat16(v.y);
    __nv_bfloat16 h2 = __float2bfloat16(v.z);
    __nv_bfloat16 h3 = __float2bfloat16(v.w);
    __nv_bfloat16 l0 = __float2bfloat16(v.x - __bfloat162float(h0));
    __nv_bfloat16 l1 = __float2bfloat16(v.y - __bfloat162float(h1));
    __nv_bfloat16 l2 = __float2bfloat16(v.z - __bfloat162float(h2));
    __nv_bfloat16 l3 = __float2bfloat16(v.w - __bfloat162float(h3));
    __nv_bfloat162 ph0; ph0.x = h0; ph0.y = h1;
    __nv_bfloat162 ph1; ph1.x = h2; ph1.y = h3;
    __nv_bfloat162 pl0; pl0.x = l0; pl0.y = l1;
    __nv_bfloat162 pl1; pl1.x = l2; pl1.y = l3;
    ((__nv_bfloat162*)(g_hi + dst))[2 * idx + 0] = ph0;
    ((__nv_bfloat162*)(g_hi + dst))[2 * idx + 1] = ph1;
    ((__nv_bfloat162*)(g_lo + dst))[2 * idx + 0] = pl0;
    ((__nv_bfloat162*)(g_lo + dst))[2 * idx + 1] = pl1;
}

// ---------------------------------------------------------------------------
// HMMA bf16-split GEMM: 3-stage cp.async pipeline, one sync per chunk.
// ---------------------------------------------------------------------------
#define BM 128
#define BN 128
#define BK 64

#define TILE_B      (128 * 128)
#define STAGE_BYTES (4 * TILE_B)          // 64 KB
#define SM_TOTAL    (3 * STAGE_BYTES)     // 192 KB

__device__ __forceinline__ void gemm_hmma(
    const __nv_bfloat16* __restrict__ ah, const __nv_bfloat16* __restrict__ al,
    const __nv_bfloat16* __restrict__ bh, const __nv_bfloat16* __restrict__ bl,
    const float* __restrict__ bias, float* __restrict__ C,
    __nv_bfloat16* __restrict__ outH, __nv_bfloat16* __restrict__ outL, float oscale,
    int K, int ldc, int bm, int bn)
{
    extern __shared__ char smem[];
    const u32 sbase = smem_u32(smem);
    const int tid  = threadIdx.x;
    const int lane = tid & 31;
    const int wid  = tid >> 5;
    const int wm   = wid & 3;
    const int wn   = wid >> 2;

    float acc[2][8][4];
    #pragma unroll
    for (int mt = 0; mt < 2; mt++)
        #pragma unroll
        for (int nt = 0; nt < 8; nt++)
            #pragma unroll
            for (int r = 0; r < 4; r++) acc[mt][nt][r] = 0.f;

    auto load_stage = [&](int c, int stage) {
        const int k0 = c * BK;
        const u32 sb = sbase + stage * STAGE_BYTES;
        #pragma unroll
        for (int t = 0; t < 16; t++) {
            int i   = tid + t * 256;
            int arr = i >> 10;
            int ch  = i & 1023;
            int row = ch >> 3;
            int cc  = ch & 7;
            u32 soff = (u32)arr * TILE_B + (u32)row * 128 + (u32)((cc ^ (row & 7)) << 4);
            const __nv_bfloat16* g;
            if (arr == 0)      g = ah + (size_t)(bm + row) * K + k0 + cc * 8;
            else if (arr == 1) g = al + (size_t)(bm + row) * K + k0 + cc * 8;
            else if (arr == 2) g = bh + (size_t)(bn + row) * K + k0 + cc * 8;
            else               g = bl + (size_t)(bn + row) * K + k0 + cc * 8;
            cp16(sb + soff, g);
        }
        cp_commit();
    };

    auto compute_stage = [&](int stage) {
        const u32 sb = sbase + stage * STAGE_BYTES;
        #pragma unroll
        for (int ks = 0; ks < 4; ks++) {
            u32 a_h[2][4], a_l[2][4], b_h[8][2], b_l[8][2];
            #pragma unroll
            for (int mt = 0; mt < 2; mt++) {
                int row = wm * 32 + mt * 16 + (lane & 15);
                u32 koff = (u32)(((2 * ks + (lane >> 4)) ^ (row & 7)) << 4);
                u32 addr = sb + (u32)row * 128 + koff;
                ldsm_x4(a_h[mt][0], a_h[mt][1], a_h[mt][2], a_h[mt][3], addr);
                ldsm_x4(a_l[mt][0], a_l[mt][1], a_l[mt][2], a_l[mt][3], addr + TILE_B);
            }
            #pragma unroll
            for (int np = 0; np < 4; np++) {
                int row = wn * 64 + np * 16 + (lane & 15);
                u32 koff = (u32)(((2 * ks + (lane >> 4)) ^ (row & 7)) << 4);
                u32 addr = sb + 2u * TILE_B + (u32)row * 128 + koff;
                u32 r0, r1, r2, r3;
                ldsm_x4(r0, r1, r2, r3, addr);
                b_h[2 * np][0] = r0; b_h[2 * np][1] = r2;
                b_h[2 * np + 1][0] = r1; b_h[2 * np + 1][1] = r3;
                ldsm_x4(r0, r1, r2, r3, addr + TILE_B);
                b_l[2 * np][0] = r0; b_l[2 * np][1] = r2;
                b_l[2 * np + 1][0] = r1; b_l[2 * np + 1][1] = r3;
            }
            #pragma unroll
            for (int mt = 0; mt < 2; mt++)
                #pragma unroll
                for (int nt = 0; nt < 8; nt++) {
                    mma_bf16(acc[mt][nt], a_h[mt], b_h[nt]);
                    mma_bf16(acc[mt][nt], a_h[mt], b_l[nt]);
                    mma_bf16(acc[mt][nt], a_l[mt], b_h[nt]);
                }
        }
    };

    const int nch = K >> 6;        // >= 8 always here
    load_stage(0, 0);
    load_stage(1, 1);
    int cur = 0;                   // stage of chunk c
    for (int c = 0; c < nch; c++) {
        if (c == nch - 1) {
            asm volatile("cp.async.wait_group 0;" ::: "memory");
        } else {
            asm volatile("cp.async.wait_group 1;" ::: "memory");
        }
        __syncthreads();
        if (c + 2 < nch) {
            int nxt2 = cur + 2; if (nxt2 >= 3) nxt2 -= 3;
            load_stage(c + 2, nxt2);
        }
        compute_stage(cur);
        if (++cur == 3) cur = 0;
    }

    const int g  = lane >> 2;
    const int tc = lane & 3;
    if (outH) {
        #pragma unroll
        for (int mt = 0; mt < 2; mt++) {
            #pragma unroll
            for (int nt = 0; nt < 8; nt++) {
                int row = bm + wm * 32 + mt * 16 + g;
                int col = bn + wn * 64 + nt * 8 + 2 * tc;
                float b0 = bias[col], b1 = bias[col + 1];
                float f0 = (acc[mt][nt][0] + b0) * oscale;
                float f1 = (acc[mt][nt][1] + b1) * oscale;
                float f2 = (acc[mt][nt][2] + b0) * oscale;
                float f3 = (acc[mt][nt][3] + b1) * oscale;
                u32 lo01, lo23;
                u32 hi01 = pack_split(f0, f1, lo01);
                u32 hi23 = pack_split(f2, f3, lo23);
                size_t o0 = (size_t)row * ldc + col;
                size_t o1 = (size_t)(row + 8) * ldc + col;
                *(u32*)&outH[o0] = hi01; *(u32*)&outL[o0] = lo01;
                *(u32*)&outH[o1] = hi23; *(u32*)&outL[o1] = lo23;
            }
        }
    } else {
        #pragma unroll
        for (int mt = 0; mt < 2; mt++) {
            #pragma unroll
            for (int nt = 0; nt < 8; nt++) {
                int row = bm + wm * 32 + mt * 16 + g;
                int col = bn + wn * 64 + nt * 8 + 2 * tc;
                float b0 = bias[col], b1 = bias[col + 1];
                float2 v0; v0.x = acc[mt][nt][0] + b0; v0.y = acc[mt][nt][1] + b1;
                float2 v1; v1.x = acc[mt][nt][2] + b0; v1.y = acc[mt][nt][3] + b1;
                *(float2*)&C[(size_t)row * ldc + col]       = v0;
                *(float2*)&C[(size_t)(row + 8) * ldc + col] = v1;
            }
        }
    }
}

__global__ __launch_bounds__(256) void qkv_hmma_kernel(
    const float* __restrict__ bq, const float* __restrict__ bk, const float* __restrict__ bv)
{
    const int z = blockIdx.z;
    const float* bias = (z == 0) ? bq : (z == 1) ? bk : bv;
    const float scale = (z == 0) ? 0.17677669529663687f : 1.0f;
    gemm_hmma(g_hi + X_OFF, g_lo + X_OFF,
              g_hi + W_OFF + (size_t)z * WSZ, g_lo + W_OFF + (size_t)z * WSZ,
              bias, nullptr,
              g_hi + QKV_OFF + (size_t)z * QKVSZ, g_lo + QKV_OFF + (size_t)z * QKVSZ, scale,
              D_MODEL, R_DIM, blockIdx.y * BM, blockIdx.x * BN);
}

__global__ __launch_bounds__(256) void outproj_hmma_kernel(
    const float* __restrict__ bo, float* __restrict__ out)
{
    gemm_hmma(g_hi + O_OFF, g_lo + O_OFF,
              g_hi + WO_OFF, g_lo + WO_OFF,
              bo, out, nullptr, nullptr, 1.0f,
              R_DIM, D_MODEL, blockIdx.y * BM, blockIdx.x * BN);
}

// ---------------------------------------------------------------------------
// HMMA flash attention: 3-stage cp.async KV pipeline, one sync per chunk.
// ---------------------------------------------------------------------------
#define ATT_BQ  128
#define ATT_BKV 128
#define ROWB    80

#define AQ_H   0
#define AQ_L   10240
#define ASTG0  20480
#define ASTG   41472              // stage: Kh,Kl,Vh,Vl (4*10240) + 512 mask
#define AS_KH  0
#define AS_KL  10240
#define AS_VH  20480
#define AS_VL  30720
#define AS_MSK 40960
#define ATT_SMEM (20480 + 3 * 41472)   // 144896

__global__ __launch_bounds__(256, 1) void attn_hmma_kernel(const int* __restrict__ mask)
{
    extern __shared__ char smem[];
    const u32 sb = smem_u32(smem);
    const int tid  = threadIdx.x;
    const int lane = tid & 31;
    const int w    = tid >> 5;
    const int bh   = blockIdx.y;
    const int b    = bh >> 4;
    const int h    = bh & 15;
    const int q0   = blockIdx.x * ATT_BQ;
    const int g    = lane >> 2;
    const int tc   = lane & 3;

    const __nv_bfloat16* Qh = g_hi + QKV_OFF;
    const __nv_bfloat16* Ql = g_lo + QKV_OFF;
    const __nv_bfloat16* Kh = g_hi + QKV_OFF + QKVSZ;
    const __nv_bfloat16* Kl = g_lo + QKV_OFF + QKVSZ;
    const __nv_bfloat16* Vh = g_hi + QKV_OFF + 2 * QKVSZ;
    const __nv_bfloat16* Vl = g_lo + QKV_OFF + 2 * QKVSZ;
    __nv_bfloat16* Oh = g_hi + O_OFF;
    __nv_bfloat16* Ol = g_lo + O_OFF;

    // ---- KV stage loader ----
    auto load_kv = [&](int k0, int stage) {
        const u32 stg = sb + ASTG0 + stage * ASTG;
        #pragma unroll
        for (int t = 0; t < 8; t++) {
            int c   = tid + t * 256;
            int arr = c >> 9;      // 0:Kh 1:Kl 2:Vh 3:Vl
            int wch = c & 511;
            int row = wch >> 2;
            int prt = wch & 3;
            const __nv_bfloat16* src;
            if (arr == 0)      src = Kh;
            else if (arr == 1) src = Kl;
            else if (arr == 2) src = Vh;
            else               src = Vl;
            src += (size_t)(b * S_LEN + k0 + row) * R_DIM + h * D_K + prt * 8;
            cp16(stg + arr * 10240u + (u32)row * ROWB + (u32)prt * 16, src);
        }
        if (tid < 32)
            cp16(stg + AS_MSK + tid * 16, mask + b * S_LEN + k0 + tid * 4);
        cp_commit();
    };

    // ---- prologue: Q stage, then KV stages 0 and 1 ----
    #pragma unroll
    for (int t = 0; t < 4; t++) {
        int c   = tid + t * 256;
        int arr = c >> 9;
        int wch = c & 511;
        int row = wch >> 2;
        int prt = wch & 3;
        const __nv_bfloat16* src = (arr ? Ql : Qh)
            + (size_t)(b * S_LEN + q0 + row) * R_DIM + h * D_K + prt * 8;
        cp16(sb + (arr ? AQ_L : AQ_H) + row * ROWB + prt * 16, src);
    }
    cp_commit();
    load_kv(0, 0);
    load_kv(ATT_BKV, 1);

    asm volatile("cp.async.wait_group 2;" ::: "memory");   // Q ready
    __syncthreads();

    u32 aqh[2][4], aql[2][4];
    #pragma unroll
    for (int kk = 0; kk < 2; kk++) {
        u32 addr = sb + AQ_H + (u32)(w * 16 + (lane & 15)) * ROWB + kk * 32 + (lane >> 4) * 16;
        ldsm_x4(aqh[kk][0], aqh[kk][1], aqh[kk][2], aqh[kk][3], addr);
        ldsm_x4(aql[kk][0], aql[kk][1], aql[kk][2], aql[kk][3], addr + (AQ_L - AQ_H));
    }

    float m0 = -1e30f, m1 = -1e30f, l0 = 0.f, l1 = 0.f;
    float ao[4][4];
    #pragma unroll
    for (int nt = 0; nt < 4; nt++)
        #pragma unroll
        for (int r = 0; r < 4; r++) ao[nt][r] = 0.f;

    const int nchunks = S_LEN / ATT_BKV;   // 16
    int cur = 0;
    for (int c = 0; c < nchunks; c++) {
        if (c == nchunks - 1) {
            asm volatile("cp.async.wait_group 0;" ::: "memory");
        } else {
            asm volatile("cp.async.wait_group 1;" ::: "memory");
        }
        __syncthreads();
        if (c + 2 < nchunks) {
            int nxt2 = cur + 2; if (nxt2 >= 3) nxt2 -= 3;
            load_kv((c + 2) * ATT_BKV, nxt2);
        }
        const u32 stg = sb + ASTG0 + cur * ASTG;
        const u32 stgoff = ASTG0 + cur * ASTG;

        // ---- scores ----
        float sc[16][4];
        #pragma unroll
        for (int p8 = 0; p8 < 8; p8++) {
            #pragma unroll
            for (int r = 0; r < 4; r++) { sc[2 * p8][r] = 0.f; sc[2 * p8 + 1][r] = 0.f; }
            #pragma unroll
            for (int kk = 0; kk < 2; kk++) {
                u32 addr = stg + AS_KH + (u32)(p8 * 16 + (lane & 15)) * ROWB + kk * 32 + (lane >> 4) * 16;
                u32 rh0, rh1, rh2, rh3, rl0, rl1, rl2, rl3;
                ldsm_x4(rh0, rh1, rh2, rh3, addr);
                ldsm_x4(rl0, rl1, rl2, rl3, addr + (AS_KL - AS_KH));
                u32 beh[2] = {rh0, rh2}, boh[2] = {rh1, rh3};
                u32 bel[2] = {rl0, rl2}, bol[2] = {rl1, rl3};
                mma_bf16(sc[2 * p8], aqh[kk], beh);
                mma_bf16(sc[2 * p8], aqh[kk], bel);
                mma_bf16(sc[2 * p8], aql[kk], beh);
                mma_bf16(sc[2 * p8 + 1], aqh[kk], boh);
                mma_bf16(sc[2 * p8 + 1], aqh[kk], bol);
                mma_bf16(sc[2 * p8 + 1], aql[kk], boh);
            }
        }

        // ---- online softmax ----
        float mt0 = m0, mt1 = m1;
        #pragma unroll
        for (int nt = 0; nt < 16; nt++) {
            int mi0 = *(const int*)(smem + stgoff + AS_MSK + (nt * 8 + 2 * tc) * 4);
            int mi1 = *(const int*)(smem + stgoff + AS_MSK + (nt * 8 + 2 * tc + 1) * 4);
            float md0 = mi0 ? 0.f : -1e30f;
            float md1 = mi1 ? 0.f : -1e30f;
            sc[nt][0] += md0; sc[nt][1] += md1;
            sc[nt][2] += md0; sc[nt][3] += md1;
            mt0 = fmaxf(mt0, fmaxf(sc[nt][0], sc[nt][1]));
            mt1 = fmaxf(mt1, fmaxf(sc[nt][2], sc[nt][3]));
        }
        mt0 = fmaxf(mt0, __shfl_xor_sync(0xFFFFFFFFu, mt0, 1));
        mt0 = fmaxf(mt0, __shfl_xor_sync(0xFFFFFFFFu, mt0, 2));
        mt1 = fmaxf(mt1, __shfl_xor_sync(0xFFFFFFFFu, mt1, 1));
        mt1 = fmaxf(mt1, __shfl_xor_sync(0xFFFFFFFFu, mt1, 2));
        float corr0 = __expf(m0 - mt0);
        float corr1 = __expf(m1 - mt1);
        m0 = mt0; m1 = mt1;
        float ls0 = 0.f, ls1 = 0.f;
        #pragma unroll
        for (int nt = 0; nt < 16; nt++) {
            sc[nt][0] = __expf(sc[nt][0] - m0);
            sc[nt][1] = __expf(sc[nt][1] - m0);
            sc[nt][2] = __expf(sc[nt][2] - m1);
            sc[nt][3] = __expf(sc[nt][3] - m1);
            ls0 += sc[nt][0] + sc[nt][1];
            ls1 += sc[nt][2] + sc[nt][3];
        }
        ls0 += __shfl_xor_sync(0xFFFFFFFFu, ls0, 1);
        ls0 += __shfl_xor_sync(0xFFFFFFFFu, ls0, 2);
        ls1 += __shfl_xor_sync(0xFFFFFFFFu, ls1, 1);
        ls1 += __shfl_xor_sync(0xFFFFFFFFu, ls1, 2);
        l0 = l0 * corr0 + ls0;
        l1 = l1 * corr1 + ls1;
        #pragma unroll
        for (int nt = 0; nt < 4; nt++) {
            ao[nt][0] *= corr0; ao[nt][1] *= corr0;
            ao[nt][2] *= corr1; ao[nt][3] *= corr1;
        }

        // ---- P @ V ----
        #pragma unroll
        for (int jc = 0; jc < 8; jc++) {
            u32 ah[4], al[4];
            ah[0] = pack_split(sc[2 * jc][0],     sc[2 * jc][1],     al[0]);
            ah[1] = pack_split(sc[2 * jc][2],     sc[2 * jc][3],     al[1]);
            ah[2] = pack_split(sc[2 * jc + 1][0], sc[2 * jc + 1][1], al[2]);
            ah[3] = pack_split(sc[2 * jc + 1][2], sc[2 * jc + 1][3], al[3]);
            #pragma unroll
            for (int np = 0; np < 2; np++) {
                u32 addr = stg + AS_VH
                         + (u32)(jc * 16 + ((lane >> 3) & 1) * 8 + (lane & 7)) * ROWB
                         + (u32)(np * 16 + (lane >> 4) * 8) * 2;
                u32 th0, th1, th2, th3, tl0, tl1, tl2, tl3;
                ldsm_x4_t(th0, th1, th2, th3, addr);
                ldsm_x4_t(tl0, tl1, tl2, tl3, addr + (AS_VL - AS_VH));
                u32 beh[2] = {th0, th1}, boh[2] = {th2, th3};
                u32 bel[2] = {tl0, tl1}, bol[2] = {tl2, tl3};
                mma_bf16(ao[2 * np], ah, beh);
                mma_bf16(ao[2 * np], ah, bel);
                mma_bf16(ao[2 * np], al, beh);
                mma_bf16(ao[2 * np + 1], ah, boh);
                mma_bf16(ao[2 * np + 1], ah, bol);
                mma_bf16(ao[2 * np + 1], al, boh);
            }
        }
        if (++cur == 3) cur = 0;
    }

    // ---- epilogue ----
    const float inv0 = 1.0f / l0;
    const float inv1 = 1.0f / l1;
    const int row0 = q0 + w * 16 + g;
    #pragma unroll
    for (int nt = 0; nt < 4; nt++) {
        int col = h * D_K + nt * 8 + 2 * tc;
        float f0 = ao[nt][0] * inv0, f1 = ao[nt][1] * inv0;
        float f2 = ao[nt][2] * inv1, f3 = ao[nt][3] * inv1;
        u32 lo01, lo23;
        u32 hi01 = pack_split(f0, f1, lo01);
        u32 hi23 = pack_split(f2, f3, lo23);
        size_t o0 = (size_t)(b * S_LEN + row0) * R_DIM + col;
        size_t o1 = (size_t)(b * S_LEN + row0 + 8) * R_DIM + col;
        *(u32*)&Oh[o0] = hi01;
        *(u32*)&Ol[o0] = lo01;
        *(u32*)&Oh[o1] = hi23;
        *(u32*)&Ol[o1] = lo23;
    }
}

// ---------------------------------------------------------------------------
extern "C" void kernel_launch(void* const* d_in, const int* in_sizes, int n_in,
                              void* d_out, int out_size)
{
    const float* x    = (const float*)d_in[0];
    const float* Wq   = (const float*)d_in[1];
    const float* bq   = (const float*)d_in[2];
    const float* Wk   = (const float*)d_in[3];
    const float* bk   = (const float*)d_in[4];
    const float* Wv   = (const float*)d_in[5];
    const float* bv   = (const float*)d_in[6];
    const float* Wo   = (const float*)d_in[7];
    const float* bo   = (const float*)d_in[8];
    const int*   mask = (const int*)d_in[9];
    float* out = (float*)d_out;

    cudaFuncSetAttribute(qkv_hmma_kernel, cudaFuncAttributeMaxDynamicSharedMemorySize, SM_TOTAL);
    cudaFuncSetAttribute(outproj_hmma_kernel, cudaFuncAttributeMaxDynamicSharedMemorySize, SM_TOTAL);
    cudaFuncSetAttribute(attn_hmma_kernel, cudaFuncAttributeMaxDynamicSharedMemorySize, ATT_SMEM);

    // 1) fp32 -> bf16 hi/lo splits, single fused launch (3145728 float4 total)
    convert_all_kernel<<<12288, 256>>>(x, Wq, Wk, Wv, Wo);

    // 2) QKV projections (HMMA), bf16 hi/lo output, Q pre-scaled
    dim3 g_qkv(R_DIM / BN, M_ROWS / BM, 3);
    qkv_hmma_kernel<<<g_qkv, 256, SM_TOTAL>>>(bq, bk, bv);

    // 3) flash attention (HMMA, 3-stage cp.async KV pipeline)
    dim3 g_attn(S_LEN / ATT_BQ, B_SZ * N_HEADS);
    attn_hmma_kernel<<<g_attn, 256, ATT_SMEM>>>(mask);

    // 4) output projection (HMMA)
    dim3 g_out(D_MODEL / BN, M_ROWS / BM);
    outproj_hmma_kernel<<<g_out, 256, SM_TOTAL>>>(bo, out);
}

// round 15
// speedup vs baseline: 1.0024x; 1.0004x over previous
#include <cuda_runtime.h>
#include <cuda_bf16.h>
#include <cstdint>

#define D_MODEL 2048
#define R_DIM   512
#define N_HEADS 16
#define D_K     32
#define B_SZ    2
#define S_LEN   2048
#define M_ROWS  (B_SZ * S_LEN)   // 4096

typedef unsigned long long u64;
typedef uint32_t u32;

// ---------------------------------------------------------------------------
// bf16 hi/lo split storage
// ---------------------------------------------------------------------------
#define X_OFF   0ull
#define W_OFF   8388608ull
#define WSZ     1048576ull
#define WO_OFF  11534336ull
#define O_OFF   12582912ull
#define QKV_OFF 14680064ull
#define QKVSZ   2097152ull
#define SPLIT_TOTAL 20971520ull
__device__ __nv_bfloat16 g_hi[SPLIT_TOTAL];
__device__ __nv_bfloat16 g_lo[SPLIT_TOTAL];

// ---------------------------------------------------------------------------
// PTX helpers (base ISA only: mma.sync / ldmatrix / cp.async)
// ---------------------------------------------------------------------------
__device__ __forceinline__ u32 smem_u32(const void* p) {
    u32 a;
    asm("{ .reg .u64 t; cvta.to.shared.u64 t, %1; cvt.u32.u64 %0, t; }" : "=r"(a) : "l"(p));
    return a;
}
__device__ __forceinline__ void ldsm_x4(u32& r0, u32& r1, u32& r2, u32& r3, u32 addr) {
    asm volatile("ldmatrix.sync.aligned.m8n8.x4.shared.b16 {%0,%1,%2,%3}, [%4];"
                 : "=r"(r0), "=r"(r1), "=r"(r2), "=r"(r3) : "r"(addr));
}
__device__ __forceinline__ void ldsm_x4_t(u32& r0, u32& r1, u32& r2, u32& r3, u32 addr) {
    asm volatile("ldmatrix.sync.aligned.m8n8.x4.trans.shared.b16 {%0,%1,%2,%3}, [%4];"
                 : "=r"(r0), "=r"(r1), "=r"(r2), "=r"(r3) : "r"(addr));
}
__device__ __forceinline__ void mma_bf16(float* d, const u32* a, const u32* b) {
    asm volatile(
        "mma.sync.aligned.m16n8k16.row.col.f32.bf16.bf16.f32 "
        "{%0,%1,%2,%3}, {%4,%5,%6,%7}, {%8,%9}, {%0,%1,%2,%3};"
        : "+f"(d[0]), "+f"(d[1]), "+f"(d[2]), "+f"(d[3])
        : "r"(a[0]), "r"(a[1]), "r"(a[2]), "r"(a[3]), "r"(b[0]), "r"(b[1]));
}
__device__ __forceinline__ void cp16(u32 saddr, const void* g) {
    asm volatile("cp.async.cg.shared.global [%0], [%1], 16;" :: "r"(saddr), "l"(g) : "memory");
}
__device__ __forceinline__ void cp_commit() {
    asm volatile("cp.async.commit_group;" ::: "memory");
}
__device__ __forceinline__ u32 pack_split(float x, float y, u32& lo_out) {
    __nv_bfloat162 h = __floats2bfloat162_rn(x, y);
    float hx = __bfloat162float(h.x), hy = __bfloat162float(h.y);
    __nv_bfloat162 l = __floats2bfloat162_rn(x - hx, y - hy);
    lo_out = *reinterpret_cast<u32*>(&l);
    return *reinterpret_cast<u32*>(&h);
}

// ---------------------------------------------------------------------------
// fp32 -> bf16 hi/lo split: single fused launch over x + 4 weight matrices
// segment float4 counts: x 2097152, each W 262144 (cumulative below)
// ---------------------------------------------------------------------------
__global__ __launch_bounds__(256) void convert_all_kernel(
    const float* __restrict__ x,  const float* __restrict__ Wq,
    const float* __restrict__ Wk, const float* __restrict__ Wv,
    const float* __restrict__ Wo)
{
    int i = blockIdx.x * blockDim.x + threadIdx.x;
    const float* src; size_t dst; int idx;
    if (i < 2097152)      { src = x;  dst = X_OFF;           idx = i; }
    else if (i < 2359296) { src = Wq; dst = W_OFF;           idx = i - 2097152; }
    else if (i < 2621440) { src = Wk; dst = W_OFF + WSZ;     idx = i - 2359296; }
    else if (i < 2883584) { src = Wv; dst = W_OFF + 2 * WSZ; idx = i - 2621440; }
    else                  { src = Wo; dst = WO_OFF;          idx = i - 2883584; }

    float4 v = ((const float4*)src)[idx];
    __nv_bfloat16 h0 = __float2bfloat16(v.x);
    __nv_bfloat16 h1 = __float2bfloat16(v.y);
    __nv_bfloat16 h2 = __float2bfloat16(v.z);
    __nv_bfloat16 h3 = __float2bfloat16(v.w);
    __nv_bfloat16 l0 = __float2bfloat16(v.x - __bfloat162float(h0));
    __nv_bfloat16 l1 = __float2bfloat16(v.y - __bfloat162float(h1));
    __nv_bfloat16 l2 = __float2bfloat16(v.z - __bfloat162float(h2));
    __nv_bfloat16 l3 = __float2bfloat16(v.w - __bfloat162float(h3));
    __nv_bfloat162 ph0; ph0.x = h0; ph0.y = h1;
    __nv_bfloat162 ph1; ph1.x = h2; ph1.y = h3;
    __nv_bfloat162 pl0; pl0.x = l0; pl0.y = l1;
    __nv_bfloat162 pl1; pl1.x = l2; pl1.y = l3;
    ((__nv_bfloat162*)(g_hi + dst))[2 * idx + 0] = ph0;
    ((__nv_bfloat162*)(g_hi + dst))[2 * idx + 1] = ph1;
    ((__nv_bfloat162*)(g_lo + dst))[2 * idx + 0] = pl0;
    ((__nv_bfloat162*)(g_lo + dst))[2 * idx + 1] = pl1;
}

// ---------------------------------------------------------------------------
// HMMA bf16-split GEMM: 3-stage cp.async pipeline, one sync per chunk.
// ---------------------------------------------------------------------------
#define BM 128
#define BN 128
#define BK 64

#define TILE_B      (128 * 128)
#define STAGE_BYTES (4 * TILE_B)          // 64 KB
#define SM_TOTAL    (3 * STAGE_BYTES)     // 192 KB

__device__ __forceinline__ void gemm_hmma(
    const __nv_bfloat16* __restrict__ ah, const __nv_bfloat16* __restrict__ al,
    const __nv_bfloat16* __restrict__ bh, const __nv_bfloat16* __restrict__ bl,
    const float* __restrict__ bias, float* __restrict__ C,
    __nv_bfloat16* __restrict__ outH, __nv_bfloat16* __restrict__ outL, float oscale,
    int K, int ldc, int bm, int bn)
{
    extern __shared__ char smem[];
    const u32 sbase = smem_u32(smem);
    const int tid  = threadIdx.x;
    const int lane = tid & 31;
    const int wid  = tid >> 5;
    const int wm   = wid & 3;
    const int wn   = wid >> 2;

    float acc[2][8][4];
    #pragma unroll
    for (int mt = 0; mt < 2; mt++)
        #pragma unroll
        for (int nt = 0; nt < 8; nt++)
            #pragma unroll
            for (int r = 0; r < 4; r++) acc[mt][nt][r] = 0.f;

    auto load_stage = [&](int c, int stage) {
        const int k0 = c * BK;
        const u32 sb = sbase + stage * STAGE_BYTES;
        #pragma unroll
        for (int t = 0; t < 16; t++) {
            int i   = tid + t * 256;
            int arr = i >> 10;
            int ch  = i & 1023;
            int row = ch >> 3;
            int cc  = ch & 7;
            u32 soff = (u32)arr * TILE_B + (u32)row * 128 + (u32)((cc ^ (row & 7)) << 4);
            const __nv_bfloat16* g;
            if (arr == 0)      g = ah + (size_t)(bm + row) * K + k0 + cc * 8;
            else if (arr == 1) g = al + (size_t)(bm + row) * K + k0 + cc * 8;
            else if (arr == 2) g = bh + (size_t)(bn + row) * K + k0 + cc * 8;
            else               g = bl + (size_t)(bn + row) * K + k0 + cc * 8;
            cp16(sb + soff, g);
        }
        cp_commit();
    };

    auto compute_stage = [&](int stage) {
        const u32 sb = sbase + stage * STAGE_BYTES;
        #pragma unroll
        for (int ks = 0; ks < 4; ks++) {
            u32 a_h[2][4], a_l[2][4], b_h[8][2], b_l[8][2];
            #pragma unroll
            for (int mt = 0; mt < 2; mt++) {
                int row = wm * 32 + mt * 16 + (lane & 15);
                u32 koff = (u32)(((2 * ks + (lane >> 4)) ^ (row & 7)) << 4);
                u32 addr = sb + (u32)row * 128 + koff;
                ldsm_x4(a_h[mt][0], a_h[mt][1], a_h[mt][2], a_h[mt][3], addr);
                ldsm_x4(a_l[mt][0], a_l[mt][1], a_l[mt][2], a_l[mt][3], addr + TILE_B);
            }
            #pragma unroll
            for (int np = 0; np < 4; np++) {
                int row = wn * 64 + np * 16 + (lane & 15);
                u32 koff = (u32)(((2 * ks + (lane >> 4)) ^ (row & 7)) << 4);
                u32 addr = sb + 2u * TILE_B + (u32)row * 128 + koff;
                u32 r0, r1, r2, r3;
                ldsm_x4(r0, r1, r2, r3, addr);
                b_h[2 * np][0] = r0; b_h[2 * np][1] = r2;
                b_h[2 * np + 1][0] = r1; b_h[2 * np + 1][1] = r3;
                ldsm_x4(r0, r1, r2, r3, addr + TILE_B);
                b_l[2 * np][0] = r0; b_l[2 * np][1] = r2;
                b_l[2 * np + 1][0] = r1; b_l[2 * np + 1][1] = r3;
            }
            #pragma unroll
            for (int mt = 0; mt < 2; mt++)
                #pragma unroll
                for (int nt = 0; nt < 8; nt++) {
                    mma_bf16(acc[mt][nt], a_h[mt], b_h[nt]);
                    mma_bf16(acc[mt][nt], a_h[mt], b_l[nt]);
                    mma_bf16(acc[mt][nt], a_l[mt], b_h[nt]);
                }
        }
    };

    const int nch = K >> 6;        // >= 8 always here
    load_stage(0, 0);
    load_stage(1, 1);
    int cur = 0;                   // stage of chunk c
    for (int c = 0; c < nch; c++) {
        if (c == nch - 1) {
            asm volatile("cp.async.wait_group 0;" ::: "memory");
        } else {
            asm volatile("cp.async.wait_group 1;" ::: "memory");
        }
        __syncthreads();
        if (c + 2 < nch) {
            int nxt2 = cur + 2; if (nxt2 >= 3) nxt2 -= 3;
            load_stage(c + 2, nxt2);
        }
        compute_stage(cur);
        if (++cur == 3) cur = 0;
    }

    const int g  = lane >> 2;
    const int tc = lane & 3;
    if (outH) {
        #pragma unroll
        for (int mt = 0; mt < 2; mt++) {
            #pragma unroll
            for (int nt = 0; nt < 8; nt++) {
                int row = bm + wm * 32 + mt * 16 + g;
                int col = bn + wn * 64 + nt * 8 + 2 * tc;
                float b0 = bias[col], b1 = bias[col + 1];
                float f0 = (acc[mt][nt][0] + b0) * oscale;
                float f1 = (acc[mt][nt][1] + b1) * oscale;
                float f2 = (acc[mt][nt][2] + b0) * oscale;
                float f3 = (acc[mt][nt][3] + b1) * oscale;
                u32 lo01, lo23;
                u32 hi01 = pack_split(f0, f1, lo01);
                u32 hi23 = pack_split(f2, f3, lo23);
                size_t o0 = (size_t)row * ldc + col;
                size_t o1 = (size_t)(row + 8) * ldc + col;
                *(u32*)&outH[o0] = hi01; *(u32*)&outL[o0] = lo01;
                *(u32*)&outH[o1] = hi23; *(u32*)&outL[o1] = lo23;
            }
        }
    } else {
        #pragma unroll
        for (int mt = 0; mt < 2; mt++) {
            #pragma unroll
            for (int nt = 0; nt < 8; nt++) {
                int row = bm + wm * 32 + mt * 16 + g;
                int col = bn + wn * 64 + nt * 8 + 2 * tc;
                float b0 = bias[col], b1 = bias[col + 1];
                float2 v0; v0.x = acc[mt][nt][0] + b0; v0.y = acc[mt][nt][1] + b1;
                float2 v1; v1.x = acc[mt][nt][2] + b0; v1.y = acc[mt][nt][3] + b1;
                *(float2*)&C[(size_t)row * ldc + col]       = v0;
                *(float2*)&C[(size_t)(row + 8) * ldc + col] = v1;
            }
        }
    }
}

__global__ __launch_bounds__(256) void qkv_hmma_kernel(
    const float* __restrict__ bq, const float* __restrict__ bk, const float* __restrict__ bv)
{
    const int z = blockIdx.z;
    const float* bias = (z == 0) ? bq : (z == 1) ? bk : bv;
    const float scale = (z == 0) ? 0.17677669529663687f : 1.0f;
    gemm_hmma(g_hi + X_OFF, g_lo + X_OFF,
              g_hi + W_OFF + (size_t)z * WSZ, g_lo + W_OFF + (size_t)z * WSZ,
              bias, nullptr,
              g_hi + QKV_OFF + (size_t)z * QKVSZ, g_lo + QKV_OFF + (size_t)z * QKVSZ, scale,
              D_MODEL, R_DIM, blockIdx.y * BM, blockIdx.x * BN);
}

__global__ __launch_bounds__(256) void outproj_hmma_kernel(
    const float* __restrict__ bo, float* __restrict__ out)
{
    gemm_hmma(g_hi + O_OFF, g_lo + O_OFF,
              g_hi + WO_OFF, g_lo + WO_OFF,
              bo, out, nullptr, nullptr, 1.0f,
              R_DIM, D_MODEL, blockIdx.y * BM, blockIdx.x * BN);
}

// ---------------------------------------------------------------------------
// HMMA flash attention: 3-stage cp.async KV pipeline, one sync per chunk.
// ---------------------------------------------------------------------------
#define ATT_BQ  128
#define ATT_BKV 128
#define ROWB    80

#define AQ_H   0
#define AQ_L   10240
#define ASTG0  20480
#define ASTG   41472              // stage: Kh,Kl,Vh,Vl (4*10240) + 512 mask
#define AS_KH  0
#define AS_KL  10240
#define AS_VH  20480
#define AS_VL  30720
#define AS_MSK 40960
#define ATT_SMEM (20480 + 3 * 41472)   // 144896

__global__ __launch_bounds__(256, 1) void attn_hmma_kernel(const int* __restrict__ mask)
{
    extern __shared__ char smem[];
    const u32 sb = smem_u32(smem);
    const int tid  = threadIdx.x;
    const int lane = tid & 31;
    const int w    = tid >> 5;
    const int bh   = blockIdx.y;
    const int b    = bh >> 4;
    const int h    = bh & 15;
    const int q0   = blockIdx.x * ATT_BQ;
    const int g    = lane >> 2;
    const int tc   = lane & 3;

    const __nv_bfloat16* Qh = g_hi + QKV_OFF;
    const __nv_bfloat16* Ql = g_lo + QKV_OFF;
    const __nv_bfloat16* Kh = g_hi + QKV_OFF + QKVSZ;
    const __nv_bfloat16* Kl = g_lo + QKV_OFF + QKVSZ;
    const __nv_bfloat16* Vh = g_hi + QKV_OFF + 2 * QKVSZ;
    const __nv_bfloat16* Vl = g_lo + QKV_OFF + 2 * QKVSZ;
    __nv_bfloat16* Oh = g_hi + O_OFF;
    __nv_bfloat16* Ol = g_lo + O_OFF;

    // ---- KV stage loader ----
    auto load_kv = [&](int k0, int stage) {
        const u32 stg = sb + ASTG0 + stage * ASTG;
        #pragma unroll
        for (int t = 0; t < 8; t++) {
            int c   = tid + t * 256;
            int arr = c >> 9;      // 0:Kh 1:Kl 2:Vh 3:Vl
            int wch = c & 511;
            int row = wch >> 2;
            int prt = wch & 3;
            const __nv_bfloat16* src;
            if (arr == 0)      src = Kh;
            else if (arr == 1) src = Kl;
            else if (arr == 2) src = Vh;
            else               src = Vl;
            src += (size_t)(b * S_LEN + k0 + row) * R_DIM + h * D_K + prt * 8;
            cp16(stg + arr * 10240u + (u32)row * ROWB + (u32)prt * 16, src);
        }
        if (tid < 32)
            cp16(stg + AS_MSK + tid * 16, mask + b * S_LEN + k0 + tid * 4);
        cp_commit();
    };

    // ---- prologue: Q stage, then KV stages 0 and 1 ----
    #pragma unroll
    for (int t = 0; t < 4; t++) {
        int c   = tid + t * 256;
        int arr = c >> 9;
        int wch = c & 511;
        int row = wch >> 2;
        int prt = wch & 3;
        const __nv_bfloat16* src = (arr ? Ql : Qh)
            + (size_t)(b * S_LEN + q0 + row) * R_DIM + h * D_K + prt * 8;
        cp16(sb + (arr ? AQ_L : AQ_H) + row * ROWB + prt * 16, src);
    }
    cp_commit();
    load_kv(0, 0);
    load_kv(ATT_BKV, 1);

    asm volatile("cp.async.wait_group 2;" ::: "memory");   // Q ready
    __syncthreads();

    u32 aqh[2][4], aql[2][4];
    #pragma unroll
    for (int kk = 0; kk < 2; kk++) {
        u32 addr = sb + AQ_H + (u32)(w * 16 + (lane & 15)) * ROWB + kk * 32 + (lane >> 4) * 16;
        ldsm_x4(aqh[kk][0], aqh[kk][1], aqh[kk][2], aqh[kk][3], addr);
        ldsm_x4(aql[kk][0], aql[kk][1], aql[kk][2], aql[kk][3], addr + (AQ_L - AQ_H));
    }

    float m0 = -1e30f, m1 = -1e30f, l0 = 0.f, l1 = 0.f;
    float ao[4][4];
    #pragma unroll
    for (int nt = 0; nt < 4; nt++)
        #pragma unroll
        for (int r = 0; r < 4; r++) ao[nt][r] = 0.f;

    const int nchunks = S_LEN / ATT_BKV;   // 16
    int cur = 0;
    for (int c = 0; c < nchunks; c++) {
        if (c == nchunks - 1) {
            asm volatile("cp.async.wait_group 0;" ::: "memory");
        } else {
            asm volatile("cp.async.wait_group 1;" ::: "memory");
        }
        __syncthreads();
        if (c + 2 < nchunks) {
            int nxt2 = cur + 2; if (nxt2 >= 3) nxt2 -= 3;
            load_kv((c + 2) * ATT_BKV, nxt2);
        }
        const u32 stg = sb + ASTG0 + cur * ASTG;
        const u32 stgoff = ASTG0 + cur * ASTG;

        // ---- scores ----
        float sc[16][4];
        #pragma unroll
        for (int p8 = 0; p8 < 8; p8++) {
            #pragma unroll
            for (int r = 0; r < 4; r++) { sc[2 * p8][r] = 0.f; sc[2 * p8 + 1][r] = 0.f; }
            #pragma unroll
            for (int kk = 0; kk < 2; kk++) {
                u32 addr = stg + AS_KH + (u32)(p8 * 16 + (lane & 15)) * ROWB + kk * 32 + (lane >> 4) * 16;
                u32 rh0, rh1, rh2, rh3, rl0, rl1, rl2, rl3;
                ldsm_x4(rh0, rh1, rh2, rh3, addr);
                ldsm_x4(rl0, rl1, rl2, rl3, addr + (AS_KL - AS_KH));
                u32 beh[2] = {rh0, rh2}, boh[2] = {rh1, rh3};
                u32 bel[2] = {rl0, rl2}, bol[2] = {rl1, rl3};
                mma_bf16(sc[2 * p8], aqh[kk], beh);
                mma_bf16(sc[2 * p8], aqh[kk], bel);
                mma_bf16(sc[2 * p8], aql[kk], beh);
                mma_bf16(sc[2 * p8 + 1], aqh[kk], boh);
                mma_bf16(sc[2 * p8 + 1], aqh[kk], bol);
                mma_bf16(sc[2 * p8 + 1], aql[kk], boh);
            }
        }

        // ---- online softmax ----
        float mt0 = m0, mt1 = m1;
        #pragma unroll
        for (int nt = 0; nt < 16; nt++) {
            int mi0 = *(const int*)(smem + stgoff + AS_MSK + (nt * 8 + 2 * tc) * 4);
            int mi1 = *(const int*)(smem + stgoff + AS_MSK + (nt * 8 + 2 * tc + 1) * 4);
            float md0 = mi0 ? 0.f : -1e30f;
            float md1 = mi1 ? 0.f : -1e30f;
            sc[nt][0] += md0; sc[nt][1] += md1;
            sc[nt][2] += md0; sc[nt][3] += md1;
            mt0 = fmaxf(mt0, fmaxf(sc[nt][0], sc[nt][1]));
            mt1 = fmaxf(mt1, fmaxf(sc[nt][2], sc[nt][3]));
        }
        mt0 = fmaxf(mt0, __shfl_xor_sync(0xFFFFFFFFu, mt0, 1));
        mt0 = fmaxf(mt0, __shfl_xor_sync(0xFFFFFFFFu, mt0, 2));
        mt1 = fmaxf(mt1, __shfl_xor_sync(0xFFFFFFFFu, mt1, 1));
        mt1 = fmaxf(mt1, __shfl_xor_sync(0xFFFFFFFFu, mt1, 2));
        float corr0 = __expf(m0 - mt0);
        float corr1 = __expf(m1 - mt1);
        m0 = mt0; m1 = mt1;
        float ls0 = 0.f, ls1 = 0.f;
        #pragma unroll
        for (int nt = 0; nt < 16; nt++) {
            sc[nt][0] = __expf(sc[nt][0] - m0);
            sc[nt][1] = __expf(sc[nt][1] - m0);
            sc[nt][2] = __expf(sc[nt][2] - m1);
            sc[nt][3] = __expf(sc[nt][3] - m1);
            ls0 += sc[nt][0] + sc[nt][1];
            ls1 += sc[nt][2] + sc[nt][3];
        }
        ls0 += __shfl_xor_sync(0xFFFFFFFFu, ls0, 1);
        ls0 += __shfl_xor_sync(0xFFFFFFFFu, ls0, 2);
        ls1 += __shfl_xor_sync(0xFFFFFFFFu, ls1, 1);
        ls1 += __shfl_xor_sync(0xFFFFFFFFu, ls1, 2);
        l0 = l0 * corr0 + ls0;
        l1 = l1 * corr1 + ls1;
        #pragma unroll
        for (int nt = 0; nt < 4; nt++) {
            ao[nt][0] *= corr0; ao[nt][1] *= corr0;
            ao[nt][2] *= corr1; ao[nt][3] *= corr1;
        }

        // ---- P @ V ----
        #pragma unroll
        for (int jc = 0; jc < 8; jc++) {
            u32 ah[4], al[4];
            ah[0] = pack_split(sc[2 * jc][0],     sc[2 * jc][1],     al[0]);
            ah[1] = pack_split(sc[2 * jc][2],     sc[2 * jc][3],     al[1]);
            ah[2] = pack_split(sc[2 * jc + 1][0], sc[2 * jc + 1][1], al[2]);
            ah[3] = pack_split(sc[2 * jc + 1][2], sc[2 * jc + 1][3], al[3]);
            #pragma unroll
            for (int np = 0; np < 2; np++) {
                u32 addr = stg + AS_VH
                         + (u32)(jc * 16 + ((lane >> 3) & 1) * 8 + (lane & 7)) * ROWB
                         + (u32)(np * 16 + (lane >> 4) * 8) * 2;
                u32 th0, th1, th2, th3, tl0, tl1, tl2, tl3;
                ldsm_x4_t(th0, th1, th2, th3, addr);
                ldsm_x4_t(tl0, tl1, tl2, tl3, addr + (AS_VL - AS_VH));
                u32 beh[2] = {th0, th1}, boh[2] = {th2, th3};
                u32 bel[2] = {tl0, tl1}, bol[2] = {tl2, tl3};
                mma_bf16(ao[2 * np], ah, beh);
                mma_bf16(ao[2 * np], ah, bel);
                mma_bf16(ao[2 * np], al, beh);
                mma_bf16(ao[2 * np + 1], ah, boh);
                mma_bf16(ao[2 * np + 1], ah, bol);
                mma_bf16(ao[2 * np + 1], al, boh);
            }
        }
        if (++cur == 3) cur = 0;
    }

    // ---- epilogue ----
    const float inv0 = 1.0f / l0;
    const float inv1 = 1.0f / l1;
    const int row0 = q0 + w * 16 + g;
    #pragma unroll
    for (int nt = 0; nt < 4; nt++) {
        int col = h * D_K + nt * 8 + 2 * tc;
        float f0 = ao[nt][0] * inv0, f1 = ao[nt][1] * inv0;
        float f2 = ao[nt][2] * inv1, f3 = ao[nt][3] * inv1;
        u32 lo01, lo23;
        u32 hi01 = pack_split(f0, f1, lo01);
        u32 hi23 = pack_split(f2, f3, lo23);
        size_t o0 = (size_t)(b * S_LEN + row0) * R_DIM + col;
        size_t o1 = (size_t)(b * S_LEN + row0 + 8) * R_DIM + col;
        *(u32*)&Oh[o0] = hi01;
        *(u32*)&Ol[o0] = lo01;
        *(u32*)&Oh[o1] = hi23;
        *(u32*)&Ol[o1] = lo23;
    }
}

// ---------------------------------------------------------------------------
extern "C" void kernel_launch(void* const* d_in, const int* in_sizes, int n_in,
                              void* d_out, int out_size)
{
    const float* x    = (const float*)d_in[0];
    const float* Wq   = (const float*)d_in[1];
    const float* bq   = (const float*)d_in[2];
    const float* Wk   = (const float*)d_in[3];
    const float* bk   = (const float*)d_in[4];
    const float* Wv   = (const float*)d_in[5];
    const float* bv   = (const float*)d_in[6];
    const float* Wo   = (const float*)d_in[7];
    const float* bo   = (const float*)d_in[8];
    const int*   mask = (const int*)d_in[9];
    float* out = (float*)d_out;

    cudaFuncSetAttribute(qkv_hmma_kernel, cudaFuncAttributeMaxDynamicSharedMemorySize, SM_TOTAL);
    cudaFuncSetAttribute(outproj_hmma_kernel, cudaFuncAttributeMaxDynamicSharedMemorySize, SM_TOTAL);
    cudaFuncSetAttribute(attn_hmma_kernel, cudaFuncAttributeMaxDynamicSharedMemorySize, ATT_SMEM);

    // 1) fp32 -> bf16 hi/lo splits, single fused launch (3145728 float4 total)
    convert_all_kernel<<<12288, 256>>>(x, Wq, Wk, Wv, Wo);

    // 2) QKV projections (HMMA), bf16 hi/lo output, Q pre-scaled
    dim3 g_qkv(R_DIM / BN, M_ROWS / BM, 3);
    qkv_hmma_kernel<<<g_qkv, 256, SM_TOTAL>>>(bq, bk, bv);

    // 3) flash attention (HMMA, 3-stage cp.async KV pipeline)
    dim3 g_attn(S_LEN / ATT_BQ, B_SZ * N_HEADS);
    attn_hmma_kernel<<<g_attn, 256, ATT_SMEM>>>(mask);

    // 4) output projection (HMMA)
    dim3 g_out(D_MODEL / BN, M_ROWS / BM);
    outproj_hmma_kernel<<<g_out, 256, SM_TOTAL>>>(bo, out);
}